// round 8
// baseline (speedup 1.0000x reference)
#include <cuda_runtime.h>
#include <cuda_bf16.h>
#include <cstdint>

#define NN 30000
#define NE 480000
#define ET (NE + NN)
#define CC 128

// ---------------- scratch (static device globals; no allocs) ----------------
__device__ __align__(16) float g_bufA[NN * 512];   // ping
__device__ __align__(16) float g_bufB[NN * 512];   // pong
__device__ __align__(16) float g_asrc[NN * 4];
__device__ __align__(16) float g_adst[NN * 4];
__device__ int   g_esrc[NE];
__device__ int   g_edst[NE];
__device__ int   g_deg[NN];
__device__ int   g_rowptr[NN + 1];
__device__ int   g_cur[NN];
__device__ int   g_csr[ET];          // src node per CSR slot (sorted by dst)
__device__ int   g_is64;             // edge_index dtype flag (1 = int64 layout)

// ---------------- dtype probe: int64 layout => all odd int32 words are 0 ----
__global__ void probe_kernel(const int* __restrict__ ei32) {
    __shared__ int bad;
    if (threadIdx.x == 0) bad = 0;
    __syncthreads();
    for (int i = threadIdx.x; i < 4096; i += blockDim.x) {
        if (ei32[2 * i + 1] != 0) bad = 1;   // benign race; any write sets it
    }
    __syncthreads();
    if (threadIdx.x == 0) g_is64 = bad ? 0 : 1;
}

// ---------------- graph build ----------------
__global__ void zero_deg_kernel() {
    int i = blockIdx.x * blockDim.x + threadIdx.x;
    if (i < NN) g_deg[i] = 0;
}

__global__ void build_edges_kernel(const void* __restrict__ eiRaw) {
    int e = blockIdx.x * blockDim.x + threadIdx.x;
    if (e >= NE) return;
    int s, d;
    if (g_is64) {
        const long long* ei = (const long long*)eiRaw;
        s = (int)ei[e];
        d = (int)ei[NE + e];
    } else {
        const int* ei = (const int*)eiRaw;
        s = ei[e];
        d = ei[NE + e];
    }
    if ((unsigned)s >= NN) s = 0;   // defensive clamp (should never trigger)
    if ((unsigned)d >= NN) d = 0;
    g_esrc[e] = s;
    g_edst[e] = d;
    atomicAdd(&g_deg[d], 1);
}

// single-block inclusive scan over degrees (+1 self loop each), builds rowptr & cur
__global__ void scan_kernel() {
    __shared__ int sh[1024];
    __shared__ int base;
    if (threadIdx.x == 0) base = 0;
    __syncthreads();
    for (int start = 0; start < NN; start += 1024) {
        int i = start + (int)threadIdx.x;
        int v = (i < NN) ? (g_deg[i] + 1) : 0;   // +1: self loop
        sh[threadIdx.x] = v;
        __syncthreads();
        #pragma unroll
        for (int off = 1; off < 1024; off <<= 1) {
            int t = (threadIdx.x >= (unsigned)off) ? sh[threadIdx.x - off] : 0;
            __syncthreads();
            sh[threadIdx.x] += t;
            __syncthreads();
        }
        if (i < NN) {
            int incl = base + sh[threadIdx.x];
            g_rowptr[i + 1] = incl;
            g_cur[i] = incl - v;   // exclusive prefix
        }
        __syncthreads();
        if (threadIdx.x == 1023) base += sh[1023];
        __syncthreads();
    }
    if (threadIdx.x == 0) g_rowptr[0] = 0;
}

__global__ void scatter_kernel() {
    int e = blockIdx.x * blockDim.x + threadIdx.x;
    if (e < ET) {
        int s, d;
        if (e < NE) { s = g_esrc[e]; d = g_edst[e]; }
        else        { s = d = e - NE; }
        int p = atomicAdd(&g_cur[d], 1);
        if ((unsigned)p < ET) g_csr[p] = s;
    }
}

// ---------------- SGEMM: 128x128x8 tile, TM=TN=8.
// srcSel: 0 = A operand from d_in x (external), 1 = from g_bufB
// Always writes g_bufA.
__global__ __launch_bounds__(256) void sgemm128(
    const float* __restrict__ Aext, const float* __restrict__ B,
    int srcSel, int M, int N, int K)
{
    __shared__ float As[8][128];
    __shared__ float Bs[8][128];
    const float* A = (srcSel == 0) ? Aext : (const float*)g_bufB;
    float* C = g_bufA;

    int tid = threadIdx.x;
    int tx = tid & 15;          // N direction
    int ty = tid >> 4;          // M direction
    int bm = blockIdx.x * 128;
    int bn = blockIdx.y * 128;

    int aRow = tid >> 1;                 // 0..127
    int aCol = (tid & 1) * 4;            // 0 or 4
    int bRow = tid >> 5;                 // 0..7
    int bCol = (tid & 31) * 4;           // 0..124

    float acc[8][8];
    #pragma unroll
    for (int i = 0; i < 8; i++)
        #pragma unroll
        for (int j = 0; j < 8; j++) acc[i][j] = 0.f;

    for (int k0 = 0; k0 < K; k0 += 8) {
        float4 av = make_float4(0.f, 0.f, 0.f, 0.f);
        int gr = bm + aRow;
        if (gr < M) av = *(const float4*)(A + (size_t)gr * K + k0 + aCol);
        As[aCol + 0][aRow] = av.x;
        As[aCol + 1][aRow] = av.y;
        As[aCol + 2][aRow] = av.z;
        As[aCol + 3][aRow] = av.w;
        float4 bv = *(const float4*)(B + (size_t)(k0 + bRow) * N + bn + bCol);
        *(float4*)&Bs[bRow][bCol] = bv;
        __syncthreads();
        #pragma unroll
        for (int kk = 0; kk < 8; kk++) {
            float ra[8], rb[8];
            #pragma unroll
            for (int i = 0; i < 8; i++) ra[i] = As[kk][ty * 8 + i];
            #pragma unroll
            for (int j = 0; j < 8; j++) rb[j] = Bs[kk][tx * 8 + j];
            #pragma unroll
            for (int i = 0; i < 8; i++)
                #pragma unroll
                for (int j = 0; j < 8; j++)
                    acc[i][j] = fmaf(ra[i], rb[j], acc[i][j]);
        }
        __syncthreads();
    }
    #pragma unroll
    for (int i = 0; i < 8; i++) {
        int r = bm + ty * 8 + i;
        if (r < M) {
            float* cp = C + (size_t)r * N + bn + tx * 8;
            #pragma unroll
            for (int j = 0; j < 8; j += 4) {
                float4 v = make_float4(acc[i][j], acc[i][j+1], acc[i][j+2], acc[i][j+3]);
                *(float4*)(cp + j) = v;
            }
        }
    }
}

// ---------------- attention scores: one warp per (node, head); h = g_bufA ----
__global__ __launch_bounds__(256) void attn_kernel(
    const float* __restrict__ att_s, const float* __restrict__ att_d, int H)
{
    int w = (blockIdx.x * blockDim.x + threadIdx.x) >> 5;
    int lane = threadIdx.x & 31;
    if (w >= NN * H) return;
    int n = w / H, hd = w % H;
    const float* h = g_bufA;
    float4 v  = *(const float4*)(h + (size_t)n * (H * CC) + hd * CC + lane * 4);
    float4 as = *(const float4*)(att_s + hd * CC + lane * 4);
    float4 ad = *(const float4*)(att_d + hd * CC + lane * 4);
    float ds = v.x * as.x + v.y * as.y + v.z * as.z + v.w * as.w;
    float dd = v.x * ad.x + v.y * ad.y + v.z * ad.z + v.w * ad.w;
    #pragma unroll
    for (int o = 16; o; o >>= 1) {
        ds += __shfl_xor_sync(0xffffffffu, ds, o);
        dd += __shfl_xor_sync(0xffffffffu, dd, o);
    }
    if (lane == 0) { g_asrc[w] = ds; g_adst[w] = dd; }
}

// ---------------- softmax + aggregation: one warp per (node, head)
// Reads h = g_bufA. outSel: 0 -> g_bufB, 1 -> external (final output).
__global__ __launch_bounds__(256) void agg_kernel(
    const float* __restrict__ bias, float* __restrict__ outExt,
    int outSel, int H, int doRelu)
{
    int w = (blockIdx.x * blockDim.x + threadIdx.x) >> 5;
    int lane = threadIdx.x & 31;
    if (w >= NN * H) return;
    int n = w / H, hd = w % H;
    const float* h = g_bufA;
    float* out = (outSel == 0) ? g_bufB : outExt;
    int beg = g_rowptr[n], end = g_rowptr[n + 1];
    float ad = g_adst[n * H + hd];

    // pass 1: max over incoming edges (lanes strided)
    float m = -1e30f;
    for (int i = beg + lane; i < end; i += 32) {
        float s = g_asrc[g_csr[i] * H + hd] + ad;
        s = s > 0.f ? s : 0.2f * s;
        m = fmaxf(m, s);
    }
    #pragma unroll
    for (int o = 16; o; o >>= 1) m = fmaxf(m, __shfl_xor_sync(0xffffffffu, m, o));

    // pass 2: sum of exp
    float sum = 0.f;
    for (int i = beg + lane; i < end; i += 32) {
        float s = g_asrc[g_csr[i] * H + hd] + ad;
        s = s > 0.f ? s : 0.2f * s;
        sum += __expf(s - m);
    }
    #pragma unroll
    for (int o = 16; o; o >>= 1) sum += __shfl_xor_sync(0xffffffffu, sum, o);
    float inv = 1.f / sum;

    // pass 3: weighted aggregation; lanes split the 128-wide channel dim
    float4 acc = make_float4(0.f, 0.f, 0.f, 0.f);
    for (int i = beg; i < end; i++) {
        int s = g_csr[i];
        float e = g_asrc[s * H + hd] + ad;
        e = e > 0.f ? e : 0.2f * e;
        float wgt = __expf(e - m) * inv;
        float4 v = *(const float4*)(h + (size_t)s * (H * CC) + hd * CC + lane * 4);
        acc.x = fmaf(wgt, v.x, acc.x);
        acc.y = fmaf(wgt, v.y, acc.y);
        acc.z = fmaf(wgt, v.z, acc.z);
        acc.w = fmaf(wgt, v.w, acc.w);
    }
    float4 b = *(const float4*)(bias + hd * CC + lane * 4);
    acc.x += b.x; acc.y += b.y; acc.z += b.z; acc.w += b.w;
    if (doRelu) {
        acc.x = fmaxf(acc.x, 0.f);
        acc.y = fmaxf(acc.y, 0.f);
        acc.z = fmaxf(acc.z, 0.f);
        acc.w = fmaxf(acc.w, 0.f);
    }
    *(float4*)(out + (size_t)n * (H * CC) + hd * CC + lane * 4) = acc;
}

// ---------------- launch: ONLY kernel launches, no other CUDA API ----------------
extern "C" void kernel_launch(void* const* d_in, const int* in_sizes, int n_in,
                              void* d_out, int out_size)
{
    (void)in_sizes; (void)n_in; (void)out_size;
    const float* x   = (const float*)d_in[0];
    const void*  ei  = d_in[1];
    const float* W1  = (const float*)d_in[2];
    const float* as1 = (const float*)d_in[3];
    const float* ad1 = (const float*)d_in[4];
    const float* b1  = (const float*)d_in[5];
    const float* W2  = (const float*)d_in[6];
    const float* as2 = (const float*)d_in[7];
    const float* ad2 = (const float*)d_in[8];
    const float* b2  = (const float*)d_in[9];
    const float* W3  = (const float*)d_in[10];
    const float* as3 = (const float*)d_in[11];
    const float* ad3 = (const float*)d_in[12];
    const float* b3  = (const float*)d_in[13];
    float* out = (float*)d_out;

    // graph build (per launch; deterministic work)
    probe_kernel<<<1, 256>>>((const int*)ei);
    zero_deg_kernel<<<(NN + 255) / 256, 256>>>();
    build_edges_kernel<<<(NE + 255) / 256, 256>>>(ei);
    scan_kernel<<<1, 1024>>>();
    scatter_kernel<<<(ET + 255) / 256, 256>>>();

    const int MB = (NN + 127) / 128;   // 235
    dim3 gemm_g4(MB, 4);               // N=512
    dim3 gemm_g1(MB, 1);               // N=128
    int warps4_blocks = (NN * 4 * 32 + 255) / 256;
    int warps1_blocks = (NN * 1 * 32 + 255) / 256;

    // Layer 1: Fin=256 -> 4x128, relu.  A = x (external), C = bufA
    sgemm128<<<gemm_g4, 256>>>(x, W1, 0, NN, 512, 256);
    attn_kernel<<<warps4_blocks, 256>>>(as1, ad1, 4);
    agg_kernel<<<warps4_blocks, 256>>>(b1, out, 0, 4, 1);   // -> bufB

    // Layer 2: 512 -> 4x128, relu.  A = bufB, C = bufA
    sgemm128<<<gemm_g4, 256>>>(x, W2, 1, NN, 512, 512);
    attn_kernel<<<warps4_blocks, 256>>>(as2, ad2, 4);
    agg_kernel<<<warps4_blocks, 256>>>(b2, out, 0, 4, 1);   // -> bufB

    // Layer 3: 512 -> 128, single head, no relu.  A = bufB, C = bufA
    sgemm128<<<gemm_g1, 256>>>(x, W3, 1, NN, 128, 512);
    attn_kernel<<<warps1_blocks, 256>>>(as3, ad3, 1);
    agg_kernel<<<warps1_blocks, 256>>>(b3, out, 1, 1, 0);   // -> d_out
}

// round 14
// speedup vs baseline: 1.5374x; 1.5374x over previous
#include <cuda_runtime.h>
#include <cuda_bf16.h>
#include <cstdint>

#define NN 30000
#define NE 480000
#define ET (NE + NN)
#define CC 128
#define KMAX 512
#define NB_SCAN 30   // ceil(NN/1024)

// ---------------- scratch (static device globals; no allocs) ----------------
__device__ __align__(16) float g_bufA[NN * 512];   // GEMM output h
__device__ __align__(16) float g_bufB[NN * 512];   // aggregated layer output
__device__ __align__(16) float g_asrc[NN * 4];
__device__ __align__(16) float g_adst[NN * 4];
__device__ __align__(16) __nv_bfloat16 g_xhi[NN * KMAX];
__device__ __align__(16) __nv_bfloat16 g_xlo[NN * KMAX];
__device__ __align__(16) __nv_bfloat16 g_wthi[512 * 512];  // W^T [N,K]
__device__ __align__(16) __nv_bfloat16 g_wtlo[512 * 512];
__device__ int g_esrc[NE];
__device__ int g_edst[NE];
__device__ int g_deg[NN];
__device__ int g_rowptr[NN + 1];
__device__ int g_cur[NN];
__device__ int g_csr[ET];
__device__ int g_bsum[NB_SCAN];
__device__ int g_boff[NB_SCAN];
__device__ int g_is64;

// ---------------- dtype probe ----------------
__global__ void probe_kernel(const int* __restrict__ ei32) {
    __shared__ int bad;
    if (threadIdx.x == 0) bad = 0;
    __syncthreads();
    for (int i = threadIdx.x; i < 4096; i += blockDim.x)
        if (ei32[2 * i + 1] != 0) bad = 1;
    __syncthreads();
    if (threadIdx.x == 0) g_is64 = bad ? 0 : 1;
}

// ---------------- graph build ----------------
__global__ void zero_deg_kernel() {
    int i = blockIdx.x * blockDim.x + threadIdx.x;
    if (i < NN) g_deg[i] = 0;
}

__global__ void build_edges_kernel(const void* __restrict__ eiRaw) {
    int e = blockIdx.x * blockDim.x + threadIdx.x;
    if (e >= NE) return;
    int s, d;
    if (g_is64) {
        const long long* ei = (const long long*)eiRaw;
        s = (int)ei[e]; d = (int)ei[NE + e];
    } else {
        const int* ei = (const int*)eiRaw;
        s = ei[e]; d = ei[NE + e];
    }
    if ((unsigned)s >= NN) s = 0;
    if ((unsigned)d >= NN) d = 0;
    g_esrc[e] = s;
    g_edst[e] = d;
    atomicAdd(&g_deg[d], 1);
}

// 3-phase scan
__global__ __launch_bounds__(1024) void scanA_kernel() {
    int b = blockIdx.x;
    int i = b * 1024 + threadIdx.x;
    int lane = threadIdx.x & 31, warp = threadIdx.x >> 5;
    int v = (i < NN) ? (g_deg[i] + 1) : 0;
    int x = v;
    #pragma unroll
    for (int o = 1; o < 32; o <<= 1) {
        int t = __shfl_up_sync(0xffffffffu, x, o);
        if (lane >= o) x += t;
    }
    __shared__ int wsum[32];
    if (lane == 31) wsum[warp] = x;
    __syncthreads();
    if (warp == 0) {
        int y = wsum[lane];
        #pragma unroll
        for (int o = 1; o < 32; o <<= 1) {
            int t = __shfl_up_sync(0xffffffffu, y, o);
            if (lane >= o) y += t;
        }
        wsum[lane] = y;
    }
    __syncthreads();
    int incl = x + (warp ? wsum[warp - 1] : 0);
    if (i < NN) g_rowptr[i + 1] = incl;
    if (threadIdx.x == 1023) g_bsum[b] = incl;
}

__global__ void scanB_kernel() {
    int lane = threadIdx.x;
    int v = (lane < NB_SCAN) ? g_bsum[lane] : 0;
    int x = v;
    #pragma unroll
    for (int o = 1; o < 32; o <<= 1) {
        int t = __shfl_up_sync(0xffffffffu, x, o);
        if (lane >= o) x += t;
    }
    if (lane < NB_SCAN) g_boff[lane] = x - v;
}

__global__ void scanC_kernel() {
    int i = blockIdx.x * blockDim.x + threadIdx.x;
    if (i >= NN) return;
    int rp = g_rowptr[i + 1] + g_boff[i >> 10];
    g_rowptr[i + 1] = rp;
    g_cur[i] = rp - (g_deg[i] + 1);
    if (i == 0) g_rowptr[0] = 0;
}

__global__ void scatter_kernel() {
    int e = blockIdx.x * blockDim.x + threadIdx.x;
    if (e < ET) {
        int s, d;
        if (e < NE) { s = g_esrc[e]; d = g_edst[e]; }
        else        { s = d = e - NE; }
        int p = atomicAdd(&g_cur[d], 1);
        if ((unsigned)p < ET) g_csr[p] = s;
    }
}

// ---------------- fp32 -> bf16 hi/lo split ----------------
__global__ void convA_kernel(const float* __restrict__ ext, int srcSel, int total) {
    int i = blockIdx.x * blockDim.x + threadIdx.x;
    if (i >= total) return;
    float v = (srcSel == 0) ? ext[i] : g_bufB[i];
    __nv_bfloat16 hi = __float2bfloat16(v);
    float r = v - __bfloat162float(hi);
    g_xhi[i] = hi;
    g_xlo[i] = __float2bfloat16(r);
}

__global__ void convW_kernel(const float* __restrict__ W, int K, int Nt) {
    int i = blockIdx.x * blockDim.x + threadIdx.x;
    if (i >= K * Nt) return;
    int k = i / Nt, n = i % Nt;
    float v = W[i];
    __nv_bfloat16 hi = __float2bfloat16(v);
    float r = v - __bfloat162float(hi);
    g_wthi[(size_t)n * K + k] = hi;
    g_wtlo[(size_t)n * K + k] = __float2bfloat16(r);
}

// ---------------- HMMA GEMM: 128x128 tile, mma.sync m16n8k16 bf16, split 3-pass
// C[M,Ntot] = A[M,K] * W^T[Ntot,K]^T, A = g_xhi/lo, B = g_wthi/lo, C = g_bufA
#define AST 40   // SMEM row stride in bf16 (32 data + 8 pad) -> conflict-free

#define MMA16816(c, a0, a1, a2, a3, b0, b1) \
    asm volatile("mma.sync.aligned.m16n8k16.row.col.f32.bf16.bf16.f32 " \
        "{%0,%1,%2,%3}, {%4,%5,%6,%7}, {%8,%9}, {%0,%1,%2,%3};" \
        : "+f"((c)[0]), "+f"((c)[1]), "+f"((c)[2]), "+f"((c)[3]) \
        : "r"(a0), "r"(a1), "r"(a2), "r"(a3), "r"(b0), "r"(b1))

__global__ __launch_bounds__(256) void gemm_mma(int M, int Ntot, int K) {
    __shared__ __nv_bfloat16 sAh[128 * AST];
    __shared__ __nv_bfloat16 sAl[128 * AST];
    __shared__ __nv_bfloat16 sBh[128 * AST];
    __shared__ __nv_bfloat16 sBl[128 * AST];

    int tid = threadIdx.x;
    int wid = tid >> 5, lane = tid & 31;
    int wm = wid & 3, wn = wid >> 2;          // 4 x 2 warp grid
    int m0 = blockIdx.x * 128, n0 = blockIdx.y * 128;
    int gid = lane >> 2, tig = lane & 3;

    float acc[2][8][4];
    #pragma unroll
    for (int a = 0; a < 2; a++)
        #pragma unroll
        for (int b = 0; b < 8; b++)
            #pragma unroll
            for (int c = 0; c < 4; c++) acc[a][b][c] = 0.f;

    const uint4 z4 = make_uint4(0, 0, 0, 0);

    for (int k0 = 0; k0 < K; k0 += 32) {
        // ---- load chunk: A[128][32] hi/lo, B[128][32] hi/lo ----
        #pragma unroll
        for (int l = 0; l < 2; l++) {
            int idx = tid + l * 256;             // 0..511
            int r = idx >> 2, c8 = (idx & 3) << 3;
            int ra = m0 + r;
            uint4 vh = z4, vl = z4;
            if (ra < M) {
                vh = *(const uint4*)&g_xhi[(size_t)ra * K + k0 + c8];
                vl = *(const uint4*)&g_xlo[(size_t)ra * K + k0 + c8];
            }
            *(uint4*)&sAh[r * AST + c8] = vh;
            *(uint4*)&sAl[r * AST + c8] = vl;
            int rb = n0 + r;
            *(uint4*)&sBh[r * AST + c8] = *(const uint4*)&g_wthi[(size_t)rb * K + k0 + c8];
            *(uint4*)&sBl[r * AST + c8] = *(const uint4*)&g_wtlo[(size_t)rb * K + k0 + c8];
        }
        __syncthreads();

        #pragma unroll
        for (int ks = 0; ks < 2; ks++) {
            int kk = ks * 16 + tig * 2;
            uint32_t ah[2][4], al[2][4];
            #pragma unroll
            for (int mf = 0; mf < 2; mf++) {
                int rb = wm * 32 + mf * 16 + gid;
                ah[mf][0] = *(const uint32_t*)&sAh[rb * AST + kk];
                ah[mf][1] = *(const uint32_t*)&sAh[(rb + 8) * AST + kk];
                ah[mf][2] = *(const uint32_t*)&sAh[rb * AST + kk + 8];
                ah[mf][3] = *(const uint32_t*)&sAh[(rb + 8) * AST + kk + 8];
                al[mf][0] = *(const uint32_t*)&sAl[rb * AST + kk];
                al[mf][1] = *(const uint32_t*)&sAl[(rb + 8) * AST + kk];
                al[mf][2] = *(const uint32_t*)&sAl[rb * AST + kk + 8];
                al[mf][3] = *(const uint32_t*)&sAl[(rb + 8) * AST + kk + 8];
            }
            #pragma unroll
            for (int nf = 0; nf < 8; nf++) {
                int nb = wn * 64 + nf * 8 + gid;
                uint32_t bh0 = *(const uint32_t*)&sBh[nb * AST + kk];
                uint32_t bh1 = *(const uint32_t*)&sBh[nb * AST + kk + 8];
                uint32_t bl0 = *(const uint32_t*)&sBl[nb * AST + kk];
                uint32_t bl1 = *(const uint32_t*)&sBl[nb * AST + kk + 8];
                #pragma unroll
                for (int mf = 0; mf < 2; mf++) {
                    MMA16816(acc[mf][nf], ah[mf][0], ah[mf][1], ah[mf][2], ah[mf][3], bh0, bh1);
                    MMA16816(acc[mf][nf], al[mf][0], al[mf][1], al[mf][2], al[mf][3], bh0, bh1);
                    MMA16816(acc[mf][nf], ah[mf][0], ah[mf][1], ah[mf][2], ah[mf][3], bl0, bl1);
                }
            }
        }
        __syncthreads();
    }

    // ---- epilogue ----
    #pragma unroll
    for (int mf = 0; mf < 2; mf++) {
        int r0 = m0 + wm * 32 + mf * 16 + gid;
        int r1 = r0 + 8;
        #pragma unroll
        for (int nf = 0; nf < 8; nf++) {
            int c = n0 + wn * 64 + nf * 8 + tig * 2;
            if (r0 < M) {
                float2 v = make_float2(acc[mf][nf][0], acc[mf][nf][1]);
                *(float2*)&g_bufA[(size_t)r0 * Ntot + c] = v;
            }
            if (r1 < M) {
                float2 v = make_float2(acc[mf][nf][2], acc[mf][nf][3]);
                *(float2*)&g_bufA[(size_t)r1 * Ntot + c] = v;
            }
        }
    }
}

// ---------------- attention scores: one warp per (node, head); h = g_bufA ----
__global__ __launch_bounds__(256) void attn_kernel(
    const float* __restrict__ att_s, const float* __restrict__ att_d, int H)
{
    int w = (blockIdx.x * blockDim.x + threadIdx.x) >> 5;
    int lane = threadIdx.x & 31;
    if (w >= NN * H) return;
    int n = w / H, hd = w % H;
    const float* h = g_bufA;
    float4 v  = *(const float4*)(h + (size_t)n * (H * CC) + hd * CC + lane * 4);
    float4 as = *(const float4*)(att_s + hd * CC + lane * 4);
    float4 ad = *(const float4*)(att_d + hd * CC + lane * 4);
    float ds = v.x * as.x + v.y * as.y + v.z * as.z + v.w * as.w;
    float dd = v.x * ad.x + v.y * ad.y + v.z * ad.z + v.w * ad.w;
    #pragma unroll
    for (int o = 16; o; o >>= 1) {
        ds += __shfl_xor_sync(0xffffffffu, ds, o);
        dd += __shfl_xor_sync(0xffffffffu, dd, o);
    }
    if (lane == 0) { g_asrc[w] = ds; g_adst[w] = dd; }
}

// ---------------- softmax + aggregation: one warp per (node, head) ----------
__global__ __launch_bounds__(256) void agg_kernel(
    const float* __restrict__ bias, float* __restrict__ outExt,
    int outSel, int H, int doRelu)
{
    int w = (blockIdx.x * blockDim.x + threadIdx.x) >> 5;
    int lane = threadIdx.x & 31;
    if (w >= NN * H) return;
    int n = w / H, hd = w % H;
    const float* h = g_bufA;
    float* out = (outSel == 0) ? g_bufB : outExt;
    int beg = g_rowptr[n], end = g_rowptr[n + 1];
    float ad = g_adst[n * H + hd];

    float m = -1e30f;
    for (int i = beg + lane; i < end; i += 32) {
        float s = g_asrc[g_csr[i] * H + hd] + ad;
        s = s > 0.f ? s : 0.2f * s;
        m = fmaxf(m, s);
    }
    #pragma unroll
    for (int o = 16; o; o >>= 1) m = fmaxf(m, __shfl_xor_sync(0xffffffffu, m, o));

    float sum = 0.f;
    for (int i = beg + lane; i < end; i += 32) {
        float s = g_asrc[g_csr[i] * H + hd] + ad;
        s = s > 0.f ? s : 0.2f * s;
        sum += __expf(s - m);
    }
    #pragma unroll
    for (int o = 16; o; o >>= 1) sum += __shfl_xor_sync(0xffffffffu, sum, o);
    float inv = 1.f / sum;

    float4 acc = make_float4(0.f, 0.f, 0.f, 0.f);
    for (int i = beg; i < end; i++) {
        int s = g_csr[i];
        float e = g_asrc[s * H + hd] + ad;
        e = e > 0.f ? e : 0.2f * e;
        float wgt = __expf(e - m) * inv;
        float4 v = *(const float4*)(h + (size_t)s * (H * CC) + hd * CC + lane * 4);
        acc.x = fmaf(wgt, v.x, acc.x);
        acc.y = fmaf(wgt, v.y, acc.y);
        acc.z = fmaf(wgt, v.z, acc.z);
        acc.w = fmaf(wgt, v.w, acc.w);
    }
    float4 b = *(const float4*)(bias + hd * CC + lane * 4);
    acc.x += b.x; acc.y += b.y; acc.z += b.z; acc.w += b.w;
    if (doRelu) {
        acc.x = fmaxf(acc.x, 0.f);
        acc.y = fmaxf(acc.y, 0.f);
        acc.z = fmaxf(acc.z, 0.f);
        acc.w = fmaxf(acc.w, 0.f);
    }
    *(float4*)(out + (size_t)n * (H * CC) + hd * CC + lane * 4) = acc;
}

// ---------------- launch: ONLY kernel launches ----------------
extern "C" void kernel_launch(void* const* d_in, const int* in_sizes, int n_in,
                              void* d_out, int out_size)
{
    (void)in_sizes; (void)n_in; (void)out_size;
    const float* x   = (const float*)d_in[0];
    const void*  ei  = d_in[1];
    const float* W1  = (const float*)d_in[2];
    const float* as1 = (const float*)d_in[3];
    const float* ad1 = (const float*)d_in[4];
    const float* b1  = (const float*)d_in[5];
    const float* W2  = (const float*)d_in[6];
    const float* as2 = (const float*)d_in[7];
    const float* ad2 = (const float*)d_in[8];
    const float* b2  = (const float*)d_in[9];
    const float* W3  = (const float*)d_in[10];
    const float* as3 = (const float*)d_in[11];
    const float* ad3 = (const float*)d_in[12];
    const float* b3  = (const float*)d_in[13];
    float* out = (float*)d_out;

    // graph build
    probe_kernel<<<1, 256>>>((const int*)ei);
    zero_deg_kernel<<<(NN + 255) / 256, 256>>>();
    build_edges_kernel<<<(NE + 255) / 256, 256>>>(ei);
    scanA_kernel<<<NB_SCAN, 1024>>>();
    scanB_kernel<<<1, 32>>>();
    scanC_kernel<<<(NN + 255) / 256, 256>>>();
    scatter_kernel<<<(ET + 255) / 256, 256>>>();

    const int MB = (NN + 127) / 128;   // 235
    int warps4_blocks = (NN * 4 * 32 + 255) / 256;
    int warps1_blocks = (NN * 1 * 32 + 255) / 256;

    // Layer 1: x[NN,256] @ W1[256,512]
    convW_kernel<<<(256 * 512 + 255) / 256, 256>>>(W1, 256, 512);
    convA_kernel<<<(NN * 256 + 255) / 256, 256>>>(x, 0, NN * 256);
    gemm_mma<<<dim3(MB, 4), 256>>>(NN, 512, 256);
    attn_kernel<<<warps4_blocks, 256>>>(as1, ad1, 4);
    agg_kernel<<<warps4_blocks, 256>>>(b1, out, 0, 4, 1);

    // Layer 2: bufB[NN,512] @ W2[512,512]
    convW_kernel<<<(512 * 512 + 255) / 256, 256>>>(W2, 512, 512);
    convA_kernel<<<(NN * 512 + 255) / 256, 256>>>(x, 1, NN * 512);
    gemm_mma<<<dim3(MB, 4), 256>>>(NN, 512, 512);
    attn_kernel<<<warps4_blocks, 256>>>(as2, ad2, 4);
    agg_kernel<<<warps4_blocks, 256>>>(b2, out, 0, 4, 1);

    // Layer 3: bufB[NN,512] @ W3[512,128]
    convW_kernel<<<(512 * 128 + 255) / 256, 256>>>(W3, 512, 128);
    convA_kernel<<<(NN * 512 + 255) / 256, 256>>>(x, 1, NN * 512);
    gemm_mma<<<dim3(MB, 1), 256>>>(NN, 128, 512);
    attn_kernel<<<warps1_blocks, 256>>>(as3, ad3, 1);
    agg_kernel<<<warps1_blocks, 256>>>(b3, out, 1, 1, 0);
}